// round 2
// baseline (speedup 1.0000x reference)
#include <cuda_runtime.h>
#include <cstdint>

// ---------------------------------------------------------------------------
// TGN layer-graph sum embedding, fused per layer.
//   per layer k:
//     nbr_sum[n] = sum_j out[idx[k,n,j]]           (D=128 gather-sum)
//     e_sum[n]   = sum_j edge[k,n,j,:]             (DE=32)
//     t_sum[n]   = sum_j time[k,n,j,:]             (DT=32)
//     h = relu([nbr_sum|e_sum|t_sum] @ W1[k] + b1[k])
//     out_new = [out|h] @ W2[k] + b2[k]
// One kernel per layer (gather needs the full previous-layer output).
// Block = 64 nodes, 256 threads. GEMMs via register-tiled fp32 with packed
// fma.rn.f32x2 (2 MACs/instr).
// neighbor_idx dtype (int32 vs int64) is detected at runtime on-device:
// jax silently truncates the reference's requested int64 to int32 when x64
// is disabled, so we cannot trust the declared dtype.
// ---------------------------------------------------------------------------

#define DD   128   // embedding dim
#define KK   16    // neighbors
#define DE   32
#define DT   32
#define D1   192   // D + DE + DT
#define TB   64    // nodes per block
#define PA   200   // agg row pitch (floats), 16B-aligned rows
#define PC   132   // staged own-row pitch
#define PW   132   // W chunk pitch
#define NMAX 100000

typedef unsigned long long ull;

__device__ float g_buf[(size_t)NMAX * DD];   // ping-pong buffer (layer-0 output)
__device__ int   g_idx64;                    // 1 if neighbor_idx is int64

__device__ __forceinline__ ull dup2(float x) {
    ull r; asm("mov.b64 %0, {%1, %1};" : "=l"(r) : "f"(x)); return r;
}
__device__ __forceinline__ void ffma2(ull& d, ull a, ull b) {
    asm("fma.rn.f32x2 %0, %1, %2, %3;" : "=l"(d) : "l"(a), "l"(b), "l"(d));
}
__device__ __forceinline__ float2 unpk(ull v) {
    float2 r; asm("mov.b64 {%0, %1}, %2;" : "=f"(r.x), "=f"(r.y) : "l"(v)); return r;
}

// Detect index dtype: int64 buffers holding values in [0, 1e5) have every
// odd 32-bit word == 0; int32 index buffers have random values there.
__global__ void detect_idx_kernel(const int* __restrict__ p) {
    __shared__ int any;
    if (threadIdx.x == 0) any = 0;
    __syncthreads();
    int local = 0;
    for (int i = threadIdx.x; i < 4096; i += blockDim.x)
        local |= (p[2 * i + 1] != 0);
    if (local) atomicOr(&any, 1);
    __syncthreads();
    if (threadIdx.x == 0) g_idx64 = (any == 0);
}

// Accumulate acc[4 nodes][4 col-pairs] += A[TB x kRows] (shared, pitch pa)
// times W (global, [kRows][128] row-major), staged through shared in 32-row chunks.
__device__ __forceinline__ void gemm_part(
    const float* __restrict__ As, int pa,
    const float* __restrict__ Wg,
    float* __restrict__ Ws,
    int kRows,
    ull acc[4][4], int ty4, int tx8, int tid)
{
    for (int c = 0; c < kRows; c += 32) {
        const float4* srcW = (const float4*)(Wg + (size_t)c * DD);
        #pragma unroll
        for (int i = 0; i < 4; i++) {
            int f = tid + i * 256;          // float4 index 0..1023
            int r = f >> 5;
            int c4 = (f & 31) << 2;
            *(float4*)&Ws[r * PW + c4] = srcW[f];
        }
        __syncthreads();
        #pragma unroll 8
        for (int kk = 0; kk < 32; kk++) {
            const ulonglong2* wp = (const ulonglong2*)&Ws[kk * PW + tx8];
            ulonglong2 w01 = wp[0];
            ulonglong2 w23 = wp[1];
            #pragma unroll
            for (int i = 0; i < 4; i++) {
                float a = As[(ty4 + i) * pa + c + kk];
                ull ad = dup2(a);
                ffma2(acc[i][0], ad, w01.x);
                ffma2(acc[i][1], ad, w01.y);
                ffma2(acc[i][2], ad, w23.x);
                ffma2(acc[i][3], ad, w23.y);
            }
        }
        __syncthreads();
    }
}

extern "C" __global__ void __launch_bounds__(256, 2)
tgn_layer(const float* __restrict__ src,     // gather + concat source [N,128]
          const float* __restrict__ e,       // [N,K,32] (this layer)
          const float* __restrict__ t,       // [N,K,32]
          const float* __restrict__ W1g,     // [192,128]
          const float* __restrict__ b1g,     // [128]
          const float* __restrict__ W2g,     // [256,128]
          const float* __restrict__ b2g,     // [128]
          const void* __restrict__ idxRaw,   // [L,N,K] int32 or int64
          int layer,
          float* __restrict__ dst,           // [N,128]
          int N)
{
    extern __shared__ float sm[];
    float* aggS = sm;                    // TB*PA  (agg; reused for h)
    float* curS = aggS + TB * PA;        // TB*PC  (own rows)
    float* Ws   = curS + TB * PC;        // 32*PW

    const int tid  = threadIdx.x;
    const int lane = tid & 31;
    const int w    = tid >> 5;
    const int base = blockIdx.x * TB;

    const int idx64 = g_idx64;
    const long long* i64 = (const long long*)idxRaw + (size_t)layer * N * KK;
    const int*       i32 = (const int*)idxRaw       + (size_t)layer * N * KK;

    // ---------------- Phase A: aggregation ----------------
    #pragma unroll 1
    for (int i = 0; i < 8; i++) {
        int ln = w * 8 + i;
        int n  = base + ln;
        bool valid = n < N;
        float4 accA = {0.f,0.f,0.f,0.f}, accB = {0.f,0.f,0.f,0.f};
        float es = 0.f, ts = 0.f;
        float4 cv = {0.f,0.f,0.f,0.f};
        if (valid) {
            long long nb[KK];
            if (idx64) {
                #pragma unroll
                for (int j = 0; j < KK; j++) nb[j] = i64[(size_t)n * KK + j];
            } else {
                #pragma unroll
                for (int j = 0; j < KK; j++) nb[j] = i32[(size_t)n * KK + j];
            }
            #pragma unroll
            for (int j = 0; j < KK; j += 2) {
                float4 v1 = ((const float4*)(src + (size_t)nb[j]     * DD))[lane];
                float4 v2 = ((const float4*)(src + (size_t)nb[j + 1] * DD))[lane];
                accA.x += v1.x; accA.y += v1.y; accA.z += v1.z; accA.w += v1.w;
                accB.x += v2.x; accB.y += v2.y; accB.z += v2.z; accB.w += v2.w;
            }
            const float* ep = e + (size_t)n * (KK * DE);
            const float* tp = t + (size_t)n * (KK * DT);
            #pragma unroll
            for (int j = 0; j < KK; j++) {
                es += ep[j * DE + lane];
                ts += tp[j * DT + lane];
            }
            cv = ((const float4*)(src + (size_t)n * DD))[lane];
        }
        accA.x += accB.x; accA.y += accB.y; accA.z += accB.z; accA.w += accB.w;
        *(float4*)&aggS[ln * PA + lane * 4] = accA;
        aggS[ln * PA + DD + lane]        = es;
        aggS[ln * PA + DD + DE + lane]   = ts;
        *(float4*)&curS[ln * PC + lane * 4] = cv;
    }
    __syncthreads();

    // ---------------- Phase B: h = relu(agg @ W1 + b1) ----------------
    const int tx  = tid & 15;
    const int ty  = tid >> 4;
    const int tx8 = tx * 8;
    const int ty4 = ty * 4;

    ull acc[4][4];
    #pragma unroll
    for (int i = 0; i < 4; i++)
        #pragma unroll
        for (int j = 0; j < 4; j++) acc[i][j] = 0ull;

    gemm_part(aggS, PA, W1g, Ws, D1, acc, ty4, tx8, tid);

    #pragma unroll
    for (int i = 0; i < 4; i++) {
        #pragma unroll
        for (int j = 0; j < 4; j++) {
            float2 v = unpk(acc[i][j]);
            int c = tx8 + j * 2;
            aggS[(ty4 + i) * PA + c]     = fmaxf(v.x + b1g[c],     0.f);
            aggS[(ty4 + i) * PA + c + 1] = fmaxf(v.y + b1g[c + 1], 0.f);
            acc[i][j] = 0ull;
        }
    }
    __syncthreads();

    // ---------------- Phase C: out = [cur|h] @ W2 + b2 ----------------
    gemm_part(curS, PC, W2g,            Ws, DD, acc, ty4, tx8, tid);  // prev out rows
    gemm_part(aggS, PA, W2g + DD * DD,  Ws, DD, acc, ty4, tx8, tid);  // h rows

    #pragma unroll
    for (int i = 0; i < 4; i++) {
        int n = base + ty4 + i;
        if (n < N) {
            #pragma unroll
            for (int j = 0; j < 4; j++) {
                float2 v = unpk(acc[i][j]);
                int c = tx8 + j * 2;
                float2 o;
                o.x = v.x + b2g[c];
                o.y = v.y + b2g[c + 1];
                *(float2*)&dst[(size_t)n * DD + c] = o;
            }
        }
    }
}

extern "C" void kernel_launch(void* const* d_in, const int* in_sizes, int n_in,
                              void* d_out, int out_size)
{
    const float* features = (const float*)d_in[0];
    const float* edge     = (const float*)d_in[1];
    const float* timef    = (const float*)d_in[2];
    const float* W1       = (const float*)d_in[3];
    const float* b1       = (const float*)d_in[4];
    const float* W2       = (const float*)d_in[5];
    const float* b2       = (const float*)d_in[6];
    const void*  idx      = d_in[7];
    float*       out      = (float*)d_out;

    const int N = in_sizes[0] / DD;

    const size_t smem = (size_t)(TB * PA + TB * PC + 32 * PW) * sizeof(float); // 101888 B
    static int attrSet = 0;
    cudaFuncSetAttribute(tgn_layer, cudaFuncAttributeMaxDynamicSharedMemorySize, (int)smem);

    void* gptr = nullptr;
    cudaGetSymbolAddress(&gptr, g_buf);
    float* gbuf = (float*)gptr;

    const int blocks = (N + TB - 1) / TB;
    const size_t eoff = (size_t)N * KK * DE;
    const size_t toff = (size_t)N * KK * DT;

    detect_idx_kernel<<<1, 256>>>((const int*)idx);

    // layer 0: src = features -> g_buf
    tgn_layer<<<blocks, 256, smem>>>(features, edge, timef,
                                     W1, b1, W2, b2, idx, 0, gbuf, N);
    // layer 1: src = g_buf -> d_out
    tgn_layer<<<blocks, 256, smem>>>(gbuf, edge + eoff, timef + toff,
                                     W1 + D1 * DD, b1 + DD,
                                     W2 + 2 * DD * DD, b2 + DD,
                                     idx, 1, out, N);
    (void)attrSet;
}

// round 3
// speedup vs baseline: 1.2679x; 1.2679x over previous
#include <cuda_runtime.h>
#include <cstdint>

// ---------------------------------------------------------------------------
// TGN layer-graph sum embedding, fused per layer. Round 3.
//   nbr_sum[n] = sum_j src[idx[n,j]]   (D=128)
//   h  = relu([nbr_sum|e_sum|t_sum] @ W1 + b1)
//   out = [src[n]|h] @ W2 + b2
// Layout inversion vs round 2: A matrices stored TRANSPOSED in smem
// (AsT[k][node], pitch 65) so GEMM A-reads are lane-consecutive (conflict
// free) and W-reads are warp-broadcast LDS.128 (1 cyc). This removes the
// smem-crossbar bottleneck (was 320 crossbar cyc vs 128 fma cyc per SM-kk;
// now 96 vs 128 -> fma-bound).
// Block = 64 nodes, 256 threads (8 warps x 16 cols, lane = node, 2 nodes/lane).
// neighbor idx dtype (int32 vs int64) detected per-block from buffer head.
// ---------------------------------------------------------------------------

#define DD   128
#define KK   16
#define DE   32
#define DT   32
#define D1   192           // D + DE + DT
#define TB   64            // nodes per block
#define PN   65            // transposed-A pitch (nodes + pad)
#define NMAX 100000

typedef unsigned long long ull;

__device__ float g_buf[(size_t)NMAX * DD];   // layer-0 output ping buffer

__device__ __forceinline__ ull dup2(float x) {
    ull r; asm("mov.b64 %0, {%1, %1};" : "=l"(r) : "f"(x)); return r;
}
__device__ __forceinline__ void ffma2(ull& d, ull a, ull b) {
    asm("fma.rn.f32x2 %0, %1, %2, %3;" : "=l"(d) : "l"(a), "l"(b), "l"(d));
}
__device__ __forceinline__ float2 unpk(ull v) {
    float2 r; asm("mov.b64 {%0, %1}, %2;" : "=f"(r.x), "=f"(r.y) : "l"(v)); return r;
}

// GEMM accumulate: acc[2 nodes][8 col-pairs] += AsT(kRows x TB, pitch PN)^T @ W.
// AsT read lane-consecutive (conflict-free); W staged to Ws[32][128] and read
// as warp-broadcast LDS.128. W chunk c+1 prefetched to registers during the
// staging of chunk c so LDG latency hides under compute.
__device__ __forceinline__ void gemm_T(
    const float* __restrict__ AsT,   // [kRows][PN]
    const float* __restrict__ Wg,    // [kRows][128] row-major, global
    float* __restrict__ Ws,          // [32][128] staging
    int kRows,
    ull acc[2][8], int lane, int cw, int tid)
{
    float4 pre[4];
    {
        const float4* s = (const float4*)Wg;
        #pragma unroll
        for (int i = 0; i < 4; i++) pre[i] = s[tid + 256 * i];
    }
    for (int c = 0; c < kRows; c += 32) {
        // stage prefetched chunk, then prefetch next
        #pragma unroll
        for (int i = 0; i < 4; i++)
            *(float4*)&Ws[(tid + 256 * i) * 4] = pre[i];
        if (c + 32 < kRows) {
            const float4* s = (const float4*)(Wg + (size_t)(c + 32) * DD);
            #pragma unroll
            for (int i = 0; i < 4; i++) pre[i] = s[tid + 256 * i];
        }
        __syncthreads();

        const float* ap = AsT + (size_t)c * PN + lane;
        #pragma unroll 8
        for (int kk = 0; kk < 32; kk++) {
            float a0 = ap[kk * PN];
            float a1 = ap[kk * PN + 32];
            ull A0 = dup2(a0);
            ull A1 = dup2(a1);
            const ulonglong2* wp = (const ulonglong2*)(Ws + kk * DD + cw);
            ulonglong2 w0 = wp[0], w1 = wp[1], w2 = wp[2], w3 = wp[3];
            ffma2(acc[0][0], A0, w0.x); ffma2(acc[0][1], A0, w0.y);
            ffma2(acc[0][2], A0, w1.x); ffma2(acc[0][3], A0, w1.y);
            ffma2(acc[0][4], A0, w2.x); ffma2(acc[0][5], A0, w2.y);
            ffma2(acc[0][6], A0, w3.x); ffma2(acc[0][7], A0, w3.y);
            ffma2(acc[1][0], A1, w0.x); ffma2(acc[1][1], A1, w0.y);
            ffma2(acc[1][2], A1, w1.x); ffma2(acc[1][3], A1, w1.y);
            ffma2(acc[1][4], A1, w2.x); ffma2(acc[1][5], A1, w2.y);
            ffma2(acc[1][6], A1, w3.x); ffma2(acc[1][7], A1, w3.y);
        }
        __syncthreads();   // protect Ws before next chunk's STS
    }
}

extern "C" __global__ void __launch_bounds__(256, 2)
tgn_layer(const float* __restrict__ src,     // [N,128] gather+concat source
          const float* __restrict__ e,       // [N,K,32]
          const float* __restrict__ t,       // [N,K,32]
          const float* __restrict__ W1g,     // [192,128]
          const float* __restrict__ b1g,     // [128]
          const float* __restrict__ W2g,     // [256,128]
          const float* __restrict__ b2g,     // [128]
          const void* __restrict__ idxRaw,   // [L,N,K] int32 or int64
          int layer,
          float* __restrict__ dst,           // [N,128]
          int N)
{
    extern __shared__ float sm[];
    float* aggT = sm;                  // [192][PN]  (rows 0..127 reused for h^T)
    float* curT = aggT + D1 * PN;      // [128][PN]
    float* Ws   = curT + DD * PN;      // [32][128]
    __shared__ int s_flag;

    const int tid  = threadIdx.x;
    const int lane = tid & 31;
    const int w    = tid >> 5;
    const int base = blockIdx.x * TB;

    // ---- idx dtype detection from buffer head (same words for all blocks,
    // L2-resident; int64 values < 1e5 have every odd 32-bit word == 0) ----
    if (tid == 0) s_flag = 0;
    __syncthreads();
    if (tid < 64) {
        int v = ((const int*)idxRaw)[2 * tid + 1];
        if (v != 0) atomicOr(&s_flag, 1);
    }
    __syncthreads();
    const int idx64 = (s_flag == 0);

    const long long* i64 = (const long long*)idxRaw + (size_t)layer * N * KK;
    const int*       i32 = (const int*)idxRaw       + (size_t)layer * N * KK;

    // ---------------- Phase A: aggregation (writes transposed) ----------------
    #pragma unroll 1
    for (int i = 0; i < 8; i++) {
        int ln = w * 8 + i;
        int n  = base + ln;
        float4 accA = {0.f,0.f,0.f,0.f}, accB = {0.f,0.f,0.f,0.f};
        float es = 0.f, ts = 0.f;
        float4 cv = {0.f,0.f,0.f,0.f};
        if (n < N) {
            long long nb[KK];
            if (idx64) {
                #pragma unroll
                for (int j = 0; j < KK; j++) nb[j] = i64[(size_t)n * KK + j];
            } else {
                #pragma unroll
                for (int j = 0; j < KK; j++) nb[j] = i32[(size_t)n * KK + j];
            }
            #pragma unroll
            for (int j = 0; j < KK; j += 2) {
                float4 v1 = ((const float4*)(src + (size_t)nb[j]     * DD))[lane];
                float4 v2 = ((const float4*)(src + (size_t)nb[j + 1] * DD))[lane];
                accA.x += v1.x; accA.y += v1.y; accA.z += v1.z; accA.w += v1.w;
                accB.x += v2.x; accB.y += v2.y; accB.z += v2.z; accB.w += v2.w;
            }
            const float* ep = e + (size_t)n * (KK * DE);
            const float* tp = t + (size_t)n * (KK * DT);
            #pragma unroll
            for (int j = 0; j < KK; j++) {
                es += ep[j * DE + lane];
                ts += tp[j * DT + lane];
            }
            cv = ((const float4*)(src + (size_t)n * DD))[lane];
        }
        accA.x += accB.x; accA.y += accB.y; accA.z += accB.z; accA.w += accB.w;
        int r = lane * 4;
        aggT[(r + 0) * PN + ln] = accA.x;
        aggT[(r + 1) * PN + ln] = accA.y;
        aggT[(r + 2) * PN + ln] = accA.z;
        aggT[(r + 3) * PN + ln] = accA.w;
        aggT[(DD + lane) * PN + ln]      = es;
        aggT[(DD + DE + lane) * PN + ln] = ts;
        curT[(r + 0) * PN + ln] = cv.x;
        curT[(r + 1) * PN + ln] = cv.y;
        curT[(r + 2) * PN + ln] = cv.z;
        curT[(r + 3) * PN + ln] = cv.w;
    }
    __syncthreads();

    // ---------------- Phase B: h = relu(agg @ W1 + b1) ----------------
    const int cw = w * 16;    // this warp's 16 output columns
    ull acc[2][8];
    #pragma unroll
    for (int i = 0; i < 2; i++)
        #pragma unroll
        for (int j = 0; j < 8; j++) acc[i][j] = 0ull;

    gemm_T(aggT, W1g, Ws, D1, acc, lane, cw, tid);

    // epilogue 1: bias + relu, write h^T into aggT rows [cw, cw+16)
    // (gemm_T ends with __syncthreads -> all aggT reads done)
    #pragma unroll
    for (int j = 0; j < 8; j++) {
        float2 v0 = unpk(acc[0][j]);
        float2 v1 = unpk(acc[1][j]);
        int c0 = cw + 2 * j;
        float bb0 = b1g[c0], bb1 = b1g[c0 + 1];
        aggT[c0 * PN + lane]            = fmaxf(v0.x + bb0, 0.f);
        aggT[(c0 + 1) * PN + lane]      = fmaxf(v0.y + bb1, 0.f);
        aggT[c0 * PN + lane + 32]       = fmaxf(v1.x + bb0, 0.f);
        aggT[(c0 + 1) * PN + lane + 32] = fmaxf(v1.y + bb1, 0.f);
        acc[0][j] = 0ull; acc[1][j] = 0ull;
    }
    __syncthreads();

    // ---------------- Phase C: out = [cur|h] @ W2 + b2 ----------------
    gemm_T(curT, W2g,           Ws, DD, acc, lane, cw, tid);  // rows 0..127
    gemm_T(aggT, W2g + DD * DD, Ws, DD, acc, lane, cw, tid);  // rows 128..255 (h)

    #pragma unroll
    for (int half = 0; half < 2; half++) {
        int n = base + lane + half * 32;
        if (n < N) {
            float o[16];
            #pragma unroll
            for (int j = 0; j < 8; j++) {
                float2 v = unpk(acc[half][j]);
                int c = 2 * j;
                o[c]     = v.x + b2g[cw + c];
                o[c + 1] = v.y + b2g[cw + c + 1];
            }
            float* dp = dst + (size_t)n * DD + cw;
            #pragma unroll
            for (int q = 0; q < 4; q++)
                *(float4*)(dp + 4 * q) = *(float4*)&o[4 * q];
        }
    }
}

extern "C" void kernel_launch(void* const* d_in, const int* in_sizes, int n_in,
                              void* d_out, int out_size)
{
    const float* features = (const float*)d_in[0];
    const float* edge     = (const float*)d_in[1];
    const float* timef    = (const float*)d_in[2];
    const float* W1       = (const float*)d_in[3];
    const float* b1       = (const float*)d_in[4];
    const float* W2       = (const float*)d_in[5];
    const float* b2       = (const float*)d_in[6];
    const void*  idx      = d_in[7];
    float*       out      = (float*)d_out;

    const int N = in_sizes[0] / DD;

    const size_t smem = (size_t)(D1 * PN + DD * PN + 32 * DD) * sizeof(float); // 99,584 B
    cudaFuncSetAttribute(tgn_layer, cudaFuncAttributeMaxDynamicSharedMemorySize, (int)smem);

    void* gptr = nullptr;
    cudaGetSymbolAddress(&gptr, g_buf);
    float* gbuf = (float*)gptr;

    const int blocks = (N + TB - 1) / TB;
    const size_t eoff = (size_t)N * KK * DE;
    const size_t toff = (size_t)N * KK * DT;

    tgn_layer<<<blocks, 256, smem>>>(features, edge, timef,
                                     W1, b1, W2, b2, idx, 0, gbuf, N);
    tgn_layer<<<blocks, 256, smem>>>(gbuf, edge + eoff, timef + toff,
                                     W1 + D1 * DD, b1 + DD,
                                     W2 + 2 * DD * DD, b2 + DD,
                                     idx, 1, out, N);
}

// round 4
// speedup vs baseline: 1.4518x; 1.1450x over previous
#include <cuda_runtime.h>
#include <cstdint>

// ---------------------------------------------------------------------------
// TGN layer-graph sum embedding, fused per layer. Round 4.
// Changes vs round 3 (which was latency-bound: fma busy == floor but only
// 39.7% of runtime; occ 24%, nothing saturated):
//  - smem cut 99.5KB -> 64KB (drop curT; re-read own rows from L2 in phase C)
//    => 3 CTAs/SM, __launch_bounds__(256,3)
//  - XOR-swizzled transposed A layout, pitch 64: conflict-free transposed
//    writes AND lane-consecutive GEMM reads
//  - cp.async.cg for W staging (no prefetch regs, fewer L1 wavefronts)
//  - idx loads: int4-batched (int32) / 4-wide (int64); no 32-reg idx array
// ---------------------------------------------------------------------------

#define DD   128
#define KK   16
#define DE   32
#define DT   32
#define D1   192
#define TB   64
#define NMAX 100000

typedef unsigned long long ull;

__device__ float g_buf[(size_t)NMAX * DD];

__device__ __forceinline__ ull dup2(float x) {
    ull r; asm("mov.b64 %0, {%1, %1};" : "=l"(r) : "f"(x)); return r;
}
__device__ __forceinline__ void ffma2(ull& d, ull a, ull b) {
    asm("fma.rn.f32x2 %0, %1, %2, %3;" : "=l"(d) : "l"(a), "l"(b), "l"(d));
}
__device__ __forceinline__ float2 unpk(ull v) {
    float2 r; asm("mov.b64 {%0, %1}, %2;" : "=f"(r.x), "=f"(r.y) : "l"(v)); return r;
}
__device__ __forceinline__ void cpa16(uint32_t dst, const void* src) {
    asm volatile("cp.async.cg.shared.global [%0], [%1], 16;" :: "r"(dst), "l"(src));
}

// swizzled transposed-A address: feature-row r, node n (0..63)
__device__ __forceinline__ int swz(int r, int n) {
    return r * 64 + ((n & 31) ^ (r & 31)) + (n & 32);
}

// acc[2 nodes][8 col-pairs] += A(kRows x 64, swizzled)^T @ W(kRows x 128).
// W staged per 32-row chunk via cp.async; read as warp-broadcast LDS.128.
__device__ __forceinline__ void gemm_T(
    const float* __restrict__ AsT,
    const float* __restrict__ Wg,
    float* __restrict__ Ws, uint32_t wsa,
    int kRows,
    ull acc[2][8], int lane, int cw, int tid)
{
    for (int c = 0; c < kRows; c += 32) {
        const float4* s = (const float4*)(Wg + (size_t)c * DD);
        #pragma unroll
        for (int i = 0; i < 4; i++)
            cpa16(wsa + (uint32_t)(tid + 256 * i) * 16, s + tid + 256 * i);
        asm volatile("cp.async.commit_group;");
        asm volatile("cp.async.wait_group 0;");
        __syncthreads();

        const float* ap = AsT + (size_t)c * 64;
        #pragma unroll 8
        for (int kk = 0; kk < 32; kk++) {
            int sw = lane ^ kk;
            float a0 = ap[kk * 64 + sw];
            float a1 = ap[kk * 64 + sw + 32];
            ull A0 = dup2(a0);
            ull A1 = dup2(a1);
            const ulonglong2* wp = (const ulonglong2*)(Ws + kk * DD + cw);
            ulonglong2 w0 = wp[0], w1 = wp[1], w2 = wp[2], w3 = wp[3];
            ffma2(acc[0][0], A0, w0.x); ffma2(acc[0][1], A0, w0.y);
            ffma2(acc[0][2], A0, w1.x); ffma2(acc[0][3], A0, w1.y);
            ffma2(acc[0][4], A0, w2.x); ffma2(acc[0][5], A0, w2.y);
            ffma2(acc[0][6], A0, w3.x); ffma2(acc[0][7], A0, w3.y);
            ffma2(acc[1][0], A1, w0.x); ffma2(acc[1][1], A1, w0.y);
            ffma2(acc[1][2], A1, w1.x); ffma2(acc[1][3], A1, w1.y);
            ffma2(acc[1][4], A1, w2.x); ffma2(acc[1][5], A1, w2.y);
            ffma2(acc[1][6], A1, w3.x); ffma2(acc[1][7], A1, w3.y);
        }
        __syncthreads();
    }
}

extern "C" __global__ void __launch_bounds__(256, 3)
tgn_layer(const float* __restrict__ src,
          const float* __restrict__ e,
          const float* __restrict__ t,
          const float* __restrict__ W1g,
          const float* __restrict__ b1g,
          const float* __restrict__ W2g,
          const float* __restrict__ b2g,
          const void* __restrict__ idxRaw,
          int layer,
          float* __restrict__ dst,
          int N)
{
    extern __shared__ float sm[];
    float* aggT = sm;                 // [192][64] swizzled; rows 0..127 reused
    float* Ws   = aggT + D1 * 64;     // [32][128]
    __shared__ int s_flag;

    const int tid  = threadIdx.x;
    const int lane = tid & 31;
    const int w    = tid >> 5;
    const int base = blockIdx.x * TB;
    const uint32_t wsa = (uint32_t)__cvta_generic_to_shared(Ws);

    // idx dtype detection (int64 values < 1e5 -> every odd 32-bit word == 0)
    if (tid == 0) s_flag = 0;
    __syncthreads();
    if (tid < 64) {
        int v = ((const int*)idxRaw)[2 * tid + 1];
        if (v != 0) atomicOr(&s_flag, 1);
    }
    __syncthreads();
    const int idx64 = (s_flag == 0);

    const long long* i64 = (const long long*)idxRaw + (size_t)layer * N * KK;
    const int*       i32 = (const int*)idxRaw       + (size_t)layer * N * KK;

    // ---------------- Phase A: aggregation -> swizzled transposed smem ------
    #pragma unroll 1
    for (int i = 0; i < 8; i++) {
        int ln = w * 8 + i;
        int n  = base + ln;
        if (n >= N) continue;     // garbage cols for tail nodes never stored
        float4 accA = {0.f,0.f,0.f,0.f}, accB = {0.f,0.f,0.f,0.f};
        float es = 0.f, ts = 0.f;

        #pragma unroll
        for (int jj = 0; jj < 4; jj++) {
            long long q0, q1, q2, q3;
            if (idx64) {
                const long long* p = i64 + (size_t)n * KK + jj * 4;
                q0 = p[0]; q1 = p[1]; q2 = p[2]; q3 = p[3];
            } else {
                int4 v = ((const int4*)(i32 + (size_t)n * KK))[jj];
                q0 = v.x; q1 = v.y; q2 = v.z; q3 = v.w;
            }
            float4 v0 = ((const float4*)(src + (size_t)q0 * DD))[lane];
            float4 v1 = ((const float4*)(src + (size_t)q1 * DD))[lane];
            float4 v2 = ((const float4*)(src + (size_t)q2 * DD))[lane];
            float4 v3 = ((const float4*)(src + (size_t)q3 * DD))[lane];
            accA.x += v0.x; accA.y += v0.y; accA.z += v0.z; accA.w += v0.w;
            accB.x += v1.x; accB.y += v1.y; accB.z += v1.z; accB.w += v1.w;
            accA.x += v2.x; accA.y += v2.y; accA.z += v2.z; accA.w += v2.w;
            accB.x += v3.x; accB.y += v3.y; accB.z += v3.z; accB.w += v3.w;
        }
        const float* ep = e + (size_t)n * (KK * DE);
        const float* tp = t + (size_t)n * (KK * DT);
        #pragma unroll
        for (int j = 0; j < KK; j++) {
            es += ep[j * DE + lane];
            ts += tp[j * DT + lane];
        }
        accA.x += accB.x; accA.y += accB.y; accA.z += accB.z; accA.w += accB.w;

        int r0 = 4 * lane;
        aggT[swz(r0 + 0, ln)] = accA.x;
        aggT[swz(r0 + 1, ln)] = accA.y;
        aggT[swz(r0 + 2, ln)] = accA.z;
        aggT[swz(r0 + 3, ln)] = accA.w;
        aggT[swz(DD + lane, ln)]      = es;
        aggT[swz(DD + DE + lane, ln)] = ts;
    }
    __syncthreads();

    // ---------------- Phase B: h = relu(agg @ W1 + b1) ----------------------
    const int cw = w * 16;
    ull acc[2][8];
    #pragma unroll
    for (int i = 0; i < 2; i++)
        #pragma unroll
        for (int j = 0; j < 8; j++) acc[i][j] = 0ull;

    gemm_T(aggT, W1g, Ws, wsa, D1, acc, lane, cw, tid);

    // h -> aggT rows [cw, cw+16)  (all reads done: gemm_T ends with barrier)
    #pragma unroll
    for (int j = 0; j < 8; j++) {
        float2 v0 = unpk(acc[0][j]);
        float2 v1 = unpk(acc[1][j]);
        int c0 = cw + 2 * j;
        float bb0 = b1g[c0], bb1 = b1g[c0 + 1];
        int a0 = c0 * 64 + (lane ^ (c0 & 31));
        int a1 = (c0 + 1) * 64 + (lane ^ ((c0 + 1) & 31));
        aggT[a0]      = fmaxf(v0.x + bb0, 0.f);
        aggT[a1]      = fmaxf(v0.y + bb1, 0.f);
        aggT[a0 + 32] = fmaxf(v1.x + bb0, 0.f);
        aggT[a1 + 32] = fmaxf(v1.y + bb1, 0.f);
        acc[0][j] = 0ull; acc[1][j] = 0ull;
    }
    __syncthreads();

    // ---------------- Phase C1: acc += h @ W2[128:256] ----------------------
    gemm_T(aggT, W2g + DD * DD, Ws, wsa, DD, acc, lane, cw, tid);

    // ---------------- reload own rows (L2-hot) over aggT rows 0..127 --------
    {
        const float4* cp4 = (const float4*)(src + (size_t)base * DD);
        #pragma unroll
        for (int i = 0; i < 8; i++) {
            int f  = tid + 256 * i;      // 0..2047
            int n  = f >> 5;             // node 0..63
            int k4 = f & 31;
            if (base + n < N) {
                float4 v = cp4[f];
                int r = 4 * k4;
                aggT[swz(r + 0, n)] = v.x;
                aggT[swz(r + 1, n)] = v.y;
                aggT[swz(r + 2, n)] = v.z;
                aggT[swz(r + 3, n)] = v.w;
            }
        }
    }
    __syncthreads();

    // ---------------- Phase C2: acc += cur @ W2[0:128] ----------------------
    gemm_T(aggT, W2g, Ws, wsa, DD, acc, lane, cw, tid);

    #pragma unroll
    for (int half = 0; half < 2; half++) {
        int n = base + lane + half * 32;
        if (n < N) {
            float o[16];
            #pragma unroll
            for (int j = 0; j < 8; j++) {
                float2 v = unpk(acc[half][j]);
                o[2*j]     = v.x + b2g[cw + 2*j];
                o[2*j + 1] = v.y + b2g[cw + 2*j + 1];
            }
            float* dp = dst + (size_t)n * DD + cw;
            #pragma unroll
            for (int q = 0; q < 4; q++)
                *(float4*)(dp + 4 * q) = *(float4*)&o[4 * q];
        }
    }
}

extern "C" void kernel_launch(void* const* d_in, const int* in_sizes, int n_in,
                              void* d_out, int out_size)
{
    const float* features = (const float*)d_in[0];
    const float* edge     = (const float*)d_in[1];
    const float* timef    = (const float*)d_in[2];
    const float* W1       = (const float*)d_in[3];
    const float* b1       = (const float*)d_in[4];
    const float* W2       = (const float*)d_in[5];
    const float* b2       = (const float*)d_in[6];
    const void*  idx      = d_in[7];
    float*       out      = (float*)d_out;

    const int N = in_sizes[0] / DD;

    const size_t smem = (size_t)(D1 * 64 + 32 * DD) * sizeof(float);   // 65536 B
    cudaFuncSetAttribute(tgn_layer, cudaFuncAttributeMaxDynamicSharedMemorySize, (int)smem);

    void* gptr = nullptr;
    cudaGetSymbolAddress(&gptr, g_buf);
    float* gbuf = (float*)gptr;

    const int blocks = (N + TB - 1) / TB;
    const size_t eoff = (size_t)N * KK * DE;
    const size_t toff = (size_t)N * KK * DT;

    tgn_layer<<<blocks, 256, smem>>>(features, edge, timef,
                                     W1, b1, W2, b2, idx, 0, gbuf, N);
    tgn_layer<<<blocks, 256, smem>>>(gbuf, edge + eoff, timef + toff,
                                     W1 + D1 * DD, b1 + DD,
                                     W2 + 2 * DD * DD, b2 + DD,
                                     idx, 1, out, N);
}